// round 15
// baseline (speedup 1.0000x reference)
#include <cuda_runtime.h>
#include <cuda_fp16.h>
#include <mma.h>
#include <cstdint>

using namespace nvcuda;

#define HID     128
#define M_TILE  128
#define THREADS 512
#define LDH     136     // half stride: 272B ≡ 16 mod 128 -> conflict-free LDSM

// Device globals (no cudaMalloc). Zero-initialized at module load.
__device__ __half g_hh[65536 * 128];   // fp16 copy of h (rows >= n_nodes stay 0)
__device__ float  g_agg[65536];        // re-zeroed by mlp after read each replay

// silu via single-MUFU tanh: sigmoid(x) = 0.5*tanh(x/2) + 0.5
__device__ __forceinline__ float silu(float x) {
    float t;
    asm("tanh.approx.f32 %0, %1;" : "=f"(t) : "f"(x * 0.5f));
    return x * (0.5f * t + 0.5f);
}
__device__ __forceinline__ uint32_t packh2f(float a, float b) {
    __half2 h = __floats2half2_rn(a, b);
    return *reinterpret_cast<uint32_t*>(&h);
}
__device__ __forceinline__ void cp16(uint32_t dst, const void* src) {
    asm volatile("cp.async.cg.shared.global [%0], [%1], 16;" :: "r"(dst), "l"(src));
}
__device__ __forceinline__ void cp_commit() {
    asm volatile("cp.async.commit_group;" ::: "memory");
}
__device__ __forceinline__ void cp_wait0() {
    asm volatile("cp.async.wait_group 0;" ::: "memory");
}
// named barrier over one 128-thread row group (ids 1..4)
__device__ __forceinline__ void bar_group(int id) {
    asm volatile("bar.sync %0, 128;" :: "r"(id) : "memory");
}

// ---------------------------------------------------------------------------
// prep: (a) convert h -> g_hh fp16, (b) scatter-add distances into g_agg.
// Edge dtype probed (jax randint int64 demotes to int32 when x64 off).
// ---------------------------------------------------------------------------
__global__ void prep_kernel(const float* __restrict__ h,
                            const int* __restrict__ edges_i32,
                            const float* __restrict__ dist,
                            int n_nodes, int E) {
    __shared__ int sstride;
    if (threadIdx.x == 0) {
        bool all_zero = true;
        int probe = E < 16 ? E : 16;
        for (int j = 0; j < probe; j++)
            if (edges_i32[2 * j + 1] != 0) { all_zero = false; break; }
        sstride = all_zero ? 2 : 1;
    }
    __syncthreads();
    int stride = sstride;
    int gid = blockIdx.x * blockDim.x + threadIdx.x;
    int conv_n = n_nodes * 32;            // float4 units
    int scat_n = (E + 3) >> 2;
    int total = conv_n > scat_n ? conv_n : scat_n;
    for (int i = gid; i < total; i += gridDim.x * blockDim.x) {
        if (i < conv_n) {
            float4 v = __ldg((const float4*)&h[(size_t)i * 4]);
            uint2 pk;
            pk.x = packh2f(v.x, v.y);
            pk.y = packh2f(v.z, v.w);
            *reinterpret_cast<uint2*>(&g_hh[(size_t)i * 4]) = pk;
        }
        if (i < scat_n) {
            int i4 = i * 4;
            if (i4 + 3 < E) {
                float4 d = __ldg((const float4*)&dist[i4]);
                int r0, r1, r2, r3;
                if (stride == 1) {
                    int4 r = __ldg((const int4*)&edges_i32[i4]);
                    r0 = r.x; r1 = r.y; r2 = r.z; r3 = r.w;
                } else {
                    int4 ra = __ldg((const int4*)&edges_i32[2 * i4]);
                    int4 rb = __ldg((const int4*)&edges_i32[2 * i4 + 4]);
                    r0 = ra.x; r1 = ra.z; r2 = rb.x; r3 = rb.z;
                }
                atomicAdd(&g_agg[r0], d.x);
                atomicAdd(&g_agg[r1], d.y);
                atomicAdd(&g_agg[r2], d.z);
                atomicAdd(&g_agg[r3], d.w);
            } else {
                for (int j = i4; j < E; j++)
                    atomicAdd(&g_agg[edges_i32[(long long)j * stride]], dist[j]);
            }
        }
    }
}

using FragA = wmma::fragment<wmma::matrix_a, 16, 16, 16, __half, wmma::row_major>;
using FragB = wmma::fragment<wmma::matrix_b, 16, 16, 16, __half, wmma::row_major>;
using FragC = wmma::fragment<wmma::accumulator, 16, 16, 16, float>;

// acc[2][2] += A[r0..+31][0..127] @ B[0..127][c0..+31], fp16 smem, ping-pong.
__device__ __forceinline__ void gemm_fp16(const __half* __restrict__ as,
                                          const __half* __restrict__ bs,
                                          int r0, int c0, FragC acc[2][2]) {
    FragA af[2][2];
    FragB bf[2][2];
    wmma::load_matrix_sync(af[0][0], as + (size_t)r0 * LDH, LDH);
    wmma::load_matrix_sync(af[0][1], as + (size_t)(r0 + 16) * LDH, LDH);
    wmma::load_matrix_sync(bf[0][0], bs + c0, LDH);
    wmma::load_matrix_sync(bf[0][1], bs + c0 + 16, LDH);
#pragma unroll
    for (int ks = 0; ks < 8; ks++) {
        int cur = ks & 1, nxt = cur ^ 1;
        if (ks < 7) {
            int k = (ks + 1) * 16;
            wmma::load_matrix_sync(af[nxt][0], as + (size_t)r0 * LDH + k, LDH);
            wmma::load_matrix_sync(af[nxt][1], as + (size_t)(r0 + 16) * LDH + k, LDH);
            wmma::load_matrix_sync(bf[nxt][0], bs + (size_t)k * LDH + c0, LDH);
            wmma::load_matrix_sync(bf[nxt][1], bs + (size_t)k * LDH + c0 + 16, LDH);
        }
#pragma unroll
        for (int i = 0; i < 2; i++)
#pragma unroll
            for (int j = 0; j < 2; j++)
                wmma::mma_sync(acc[i][j], af[cur][i], bf[cur][j], acc[i][j]);
    }
}

// ---------------------------------------------------------------------------
// smem layout (bytes)
// ---------------------------------------------------------------------------
#define SM_W1   0                       // half[128*LDH] 34816
#define SM_W2   34816
#define SM_X0   69632
#define SM_X1   104448
#define SM_TH   139264
#define SM_W1R  174080                  // f32[128]
#define SM_B1   174592
#define SM_B2   175104
#define SM_IOTA 175616                  // f32[256]
#define SM_TOT  176640

// issue this GROUP's 32 rows of tile `base` from g_hh (fp16) into xh buffer
__device__ __forceinline__ void issue_fill_g(uint32_t xdst, int base,
                                             int g, int wtid) {
#pragma unroll
    for (int t = 0; t < 4; t++) {
        int idx = wtid + t * 128;             // 0..511: 32 rows x 16 chunks
        int m = g * 32 + (idx >> 4);
        int ch = idx & 15;
        cp16(xdst + (uint32_t)(m * LDH + ch * 8) * 2,
             &g_hh[(size_t)(base + m) * HID + ch * 8]);
    }
    cp_commit();
}

// ---------------------------------------------------------------------------
// Fused node MLP (fp16 TC, fp32 accum). 4 independent 4-warp pipelines per
// CTA; xh filled DIRECTLY in fp16 via cp.async (no convert pass); agg via
// per-thread LDG; residual from global fp32 h. 2 group barriers per tile.
//   t = silu(h@W1k + agg*w1r + b1);  out = h + t@W2 + b2
// ---------------------------------------------------------------------------
__global__ void __launch_bounds__(THREADS, 1)
mlp_kernel(const float* __restrict__ h,
           const float* __restrict__ W1, const float* __restrict__ b1,
           const float* __restrict__ W2, const float* __restrict__ b2,
           float* __restrict__ out, int n_nodes, int n_tiles)
{
    extern __shared__ char sm[];
    __half* w1h = (__half*)(sm + SM_W1);
    __half* w2h = (__half*)(sm + SM_W2);
    __half* xb[2] = { (__half*)(sm + SM_X0), (__half*)(sm + SM_X1) };
    __half* th  = (__half*)(sm + SM_TH);
    float*  w1r = (float*)(sm + SM_W1R);
    float*  b1s = (float*)(sm + SM_B1);
    float*  b2s = (float*)(sm + SM_B2);
    float*  iota = (float*)(sm + SM_IOTA);

    const int tid  = threadIdx.x;
    const int l    = tid & 31;
    const int warp = tid >> 5;
    const int g    = warp >> 2;          // row group 0..3
    const int wtid = tid & 127;
    const int bid  = g + 1;
    const int r0   = g * 32;
    const int c0   = (warp & 3) * 32;
    const uint32_t xbs[2] = { (uint32_t)__cvta_generic_to_shared(xb[0]),
                              (uint32_t)__cvta_generic_to_shared(xb[1]) };

    // prologue: each group streams its 32 rows of tile 0 (fp16, direct)
    if (blockIdx.x < n_tiles)
        issue_fill_g(xbs[0], blockIdx.x * M_TILE, g, wtid);
    else
        cp_commit();

    // ---- stage weights (fp16) + vectors (fp32) once per CTA ----
    for (int idx = tid; idx < 128 * 32; idx += THREADS) {
        int k = idx >> 5, c4 = (idx & 31) << 2;
        float4 v1 = __ldg((const float4*)&W1[k * HID + c4]);
        float4 v2 = __ldg((const float4*)&W2[k * HID + c4]);
        uint2 pk, qk;
        pk.x = packh2f(v1.x, v1.y);
        pk.y = packh2f(v1.z, v1.w);
        qk.x = packh2f(v2.x, v2.y);
        qk.y = packh2f(v2.z, v2.w);
        *reinterpret_cast<uint2*>(&w1h[(size_t)k * LDH + c4]) = pk;
        *reinterpret_cast<uint2*>(&w2h[(size_t)k * LDH + c4]) = qk;
    }
    if (tid < 32) {
        *(float4*)&w1r[tid * 4] = __ldg((const float4*)&W1[128 * HID + tid * 4]);
        *(float4*)&b1s[tid * 4] = __ldg((const float4*)&b1[tid * 4]);
        *(float4*)&b2s[tid * 4] = __ldg((const float4*)&b2[tid * 4]);
    }
    if (tid < 256) iota[tid] = (float)tid;
    __syncthreads();   // last full-CTA sync

    // decode accumulator fragment layout once (layout-agnostic)
    int dr[FragC::num_elements], dc[FragC::num_elements];
    int selB[FragC::num_elements];
    int dA, dB;
    {
        FragC idxf;
        wmma::load_matrix_sync(idxf, iota, 16, wmma::mem_row_major);
#pragma unroll
        for (int e = 0; e < idxf.num_elements; e++) {
            int v = __float2int_rn(idxf.x[e]);
            dr[e] = v >> 4;
            dc[e] = v & 15;
        }
        dA = dr[0];
        dB = dA;
#pragma unroll
        for (int e = 0; e < FragC::num_elements; e++)
            if (dr[e] != dA) dB = dr[e];
#pragma unroll
        for (int e = 0; e < FragC::num_elements; e++)
            selB[e] = (dr[e] != dA);
    }

    int it = 0;
    for (int tile = blockIdx.x; tile < n_tiles; tile += gridDim.x, it++) {
        const int base = tile * M_TILE;
        const int next = tile + gridDim.x;
        const int cur = it & 1;
        const __half* xc = xb[cur];
        const bool full = (base + M_TILE <= n_nodes);

        cp_wait0();
        bar_group(bid);   // fill visible; prev tile th reads + agg reads done

        // ---- agg values for this thread's fragment rows (LDG, hidden
        //      under GEMM1). g_agg rows beyond n_nodes are always zero. ----
        float aggA[2], aggB[2];
#pragma unroll
        for (int i = 0; i < 2; i++) {
            aggA[i] = g_agg[base + r0 + i * 16 + dA] * 0.01f;
            aggB[i] = g_agg[base + r0 + i * 16 + dB] * 0.01f;
        }

        // ---- stream next tile's group rows into the other buffer ----
        if (next < n_tiles) issue_fill_g(xbs[cur ^ 1], next * M_TILE, g, wtid);
        else cp_commit();

        // ---- GEMM1: D1 = X[group rows] @ W1[:128] ----
        FragC acc[2][2];
#pragma unroll
        for (int i = 0; i < 2; i++)
#pragma unroll
            for (int j = 0; j < 2; j++) wmma::fill_fragment(acc[i][j], 0.0f);
        gemm_fp16(xc, w1h, r0, c0, acc);

        // ---- epilogue1: th = silu(D1 + agg[r]*w1r[c] + b1[c]) ----
#pragma unroll
        for (int i = 0; i < 2; i++)
#pragma unroll
            for (int j = 0; j < 2; j++)
#pragma unroll
                for (int e = 0; e < FragC::num_elements; e += 2) {
                    int r = r0 + i * 16 + dr[e];
                    int c = c0 + j * 16 + dc[e];
                    bool paired = (dr[e + 1] == dr[e]) &&
                                  (dc[e + 1] == dc[e] + 1) && ((c & 1) == 0);
                    float aggv = selB[e] ? aggB[i] : aggA[i];
                    float v0 = acc[i][j].x[e] + aggv * w1r[c] + b1s[c];
                    if (paired) {
                        float v1 = acc[i][j].x[e + 1] + aggv * w1r[c + 1] + b1s[c + 1];
                        *(__half2*)&th[(size_t)r * LDH + c] =
                            __floats2half2_rn(silu(v0), silu(v1));
                    } else {
                        th[(size_t)r * LDH + c] = __float2half_rn(silu(v0));
                        int r1 = r0 + i * 16 + dr[e + 1];
                        int c1 = c0 + j * 16 + dc[e + 1];
                        float av1 = selB[e + 1] ? aggB[i] : aggA[i];
                        float v1 = acc[i][j].x[e + 1] + av1 * w1r[c1] + b1s[c1];
                        th[(size_t)r1 * LDH + c1] = __float2half_rn(silu(v1));
                    }
                }

        // ---- residual straight from GLOBAL h (fp32) into acc2 ----
        FragC acc2[2][2];
        if (full) {
#pragma unroll
            for (int i = 0; i < 2; i++)
#pragma unroll
                for (int j = 0; j < 2; j++)
                    wmma::load_matrix_sync(acc2[i][j],
                        &h[(size_t)(base + r0 + i * 16) * HID + c0 + j * 16],
                        HID, wmma::mem_row_major);
        } else {
#pragma unroll
            for (int i = 0; i < 2; i++)
#pragma unroll
                for (int j = 0; j < 2; j++) wmma::fill_fragment(acc2[i][j], 0.0f);
        }

        bar_group(bid);   // th complete; ALL warps' agg reads complete

        // ---- re-zero this group's g_agg rows (safe: post-barrier),
        //      one warp per group, one lane per row; overlaps GEMM2 ----
        if ((warp & 3) == 0 && (l & 3) == 0) {
#pragma unroll
            for (int i = 0; i < 2; i++) {
                g_agg[base + r0 + i * 16 + dA] = 0.f;
                g_agg[base + r0 + i * 16 + dB] = 0.f;
            }
        }

        // ---- GEMM2: out = residual + T[group rows] @ W2 (+ b2) ----
        gemm_fp16(th, w2h, r0, c0, acc2);

        if (full) {
#pragma unroll
            for (int i = 0; i < 2; i++)
#pragma unroll
                for (int j = 0; j < 2; j++) {
#pragma unroll
                    for (int e = 0; e < FragC::num_elements; e++)
                        acc2[i][j].x[e] += b2s[c0 + j * 16 + dc[e]];
                    wmma::store_matrix_sync(
                        &out[(size_t)(base + r0 + i * 16) * HID + c0 + j * 16],
                        acc2[i][j], HID, wmma::mem_row_major);
                }
        } else {
            // partial last tile: guarded scalar stores with residual from gmem
#pragma unroll
            for (int i = 0; i < 2; i++)
#pragma unroll
                for (int j = 0; j < 2; j++)
#pragma unroll
                    for (int e = 0; e < FragC::num_elements; e++) {
                        int gn = base + r0 + i * 16 + dr[e];
                        int c  = c0 + j * 16 + dc[e];
                        if (gn < n_nodes)
                            out[(size_t)gn * HID + c] =
                                __ldg(&h[(size_t)gn * HID + c]) +
                                acc2[i][j].x[e] + b2s[c];
                    }
        }
    }
}

// ---------------------------------------------------------------------------
extern "C" void kernel_launch(void* const* d_in, const int* in_sizes, int n_in,
                              void* d_out, int out_size) {
    const float* h    = (const float*)d_in[0];
    const int*   edg  = (const int*)  d_in[1];
    const float* dist = (const float*)d_in[2];
    const float* W1   = (const float*)d_in[9];   // W_n1 [129,128]
    const float* b1   = (const float*)d_in[10];
    const float* W2   = (const float*)d_in[11];  // W_n2 [128,128]
    const float* b2   = (const float*)d_in[12];
    float* out = (float*)d_out;

    int n_nodes = in_sizes[0] / HID;
    int E       = in_sizes[2];

    int conv_n = n_nodes * 32;
    int scat_n = (E + 3) / 4;
    int total  = conv_n > scat_n ? conv_n : scat_n;
    prep_kernel<<<(total + 255) / 256, 256>>>(h, edg, dist, n_nodes, E);

    cudaFuncSetAttribute(mlp_kernel,
                         cudaFuncAttributeMaxDynamicSharedMemorySize, SM_TOT);
    int sms = 148;
    cudaDeviceGetAttribute(&sms, cudaDevAttrMultiProcessorCount, 0);
    int n_tiles = (n_nodes + M_TILE - 1) / M_TILE;
    int grid = n_tiles < sms ? n_tiles : sms;
    mlp_kernel<<<grid, THREADS, SM_TOT>>>(h, W1, b1, W2, b2, out,
                                          n_nodes, n_tiles);
}